// round 16
// baseline (speedup 1.0000x reference)
#include <cuda_runtime.h>
#include <cuda_fp16.h>
#include <cstdint>
#include <math.h>

#define B_  8
#define C_  1024
#define CI_ 512
#define N_  4096
#define M_  1024

// ======================= scratch (device globals) =======================
__device__ __align__(1024) __half s_xT[(size_t)B_*N_*C_];     // [b][n][c]
__device__ __align__(1024) __half s_pxT[(size_t)B_*M_*C_];    // [b][m][c]
__device__ __align__(1024) __half s_wth[CI_*C_];              // scaled by Ci^-0.5
__device__ __align__(1024) __half s_wph[CI_*C_];
__device__ __align__(1024) __half s_wg[CI_*C_];
__device__ __align__(1024) __half s_wo[C_*CI_];
__device__ __align__(1024) float  s_bth[CI_];                 // scaled b_theta
__device__ __align__(1024) __half s_thT[(size_t)B_*N_*CI_];   // [b][n][ci]
__device__ __align__(1024) __half s_phT[(size_t)B_*M_*CI_];   // [b][m][ci]
__device__ __align__(1024) __half s_gdev[(size_t)B_*CI_*M_];  // centered g fp16
__device__ __align__(1024) __half s_scoresh[(size_t)B_*N_*M_];// fp16 pre-scaled scores
__device__ __align__(1024) __half s_p[(size_t)B_*N_*M_];
__device__ __align__(1024) __half s_tdev[(size_t)B_*N_*CI_];
__device__ __align__(1024) float  s_pxsum[B_*C_];
__device__ __align__(1024) float  s_psum[B_*M_];
__device__ __align__(1024) float  s_gbias[B_*CI_];            // -(w_g.pxsum)/M
__device__ __align__(1024) float  s_gmeanZ[B_*CI_];           // (w_g.pxsum)/M + b_g
__device__ __align__(1024) float  s_negtq[B_*CI_];
__device__ __align__(1024) float  s_tmean[B_*CI_];
__device__ __align__(1024) float  s_ymean[B_*C_];
__device__ __align__(1024) __half s_ydev[(size_t)B_*N_*C_];   // fp16 ydev
__device__ __align__(1024) float  s_bnpart[B_*2*C_];          // per-z col sum/sumsq of ydev
__device__ float  s_bnstat[2*C_];

// ======================= helpers =======================
__device__ __forceinline__ uint32_t smem_u32(const void* p){
    uint32_t a;
    asm("{ .reg .u64 t; cvta.to.shared.u64 t, %1; cvt.u32.u64 %0, t; }" : "=r"(a) : "l"(p));
    return a;
}
__device__ __forceinline__ void cpasync16(uint32_t dst, const void* src){
    asm volatile("cp.async.cg.shared.global [%0], [%1], 16;" :: "r"(dst), "l"(src));
}
__device__ __forceinline__ void ldsm4(uint32_t* r, uint32_t addr){
    asm volatile("ldmatrix.sync.aligned.m8n8.x4.shared.b16 {%0,%1,%2,%3}, [%4];"
        : "=r"(r[0]), "=r"(r[1]), "=r"(r[2]), "=r"(r[3]) : "r"(addr));
}
__device__ __forceinline__ void mma_hf(float* c, const uint32_t* a, const uint32_t* b){
    asm volatile("mma.sync.aligned.m16n8k16.row.col.f32.f16.f16.f32 "
        "{%0,%1,%2,%3},{%4,%5,%6,%7},{%8,%9},{%0,%1,%2,%3};"
        : "+f"(c[0]), "+f"(c[1]), "+f"(c[2]), "+f"(c[3])
        : "r"(a[0]), "r"(a[1]), "r"(a[2]), "r"(a[3]), "r"(b[0]), "r"(b[1]));
}
__device__ __forceinline__ uint32_t pack_h2(float x, float y){
    __half2 t = __floats2half2_rn(x, y);
    return *reinterpret_cast<uint32_t*>(&t);
}

#define PITCH 80

// ======================= fp16 GEMM (3-stage, 2 CTAs/SM) =======================
// D[m][n] = sum_k A[m][k]*B[n][k] (+bias). CTA 128x256, Kc=32, 8 warps.
// bias_mode: 0 none, 1 row, 2 col, 3 per-z col (bias[z*zs+col]), 4 per-z row.
// OUTMODE 0: fp32 ; 1: fp16
#define HF_OFF_A  0u
#define HF_OFF_B  10240u
#define HF_STAGE  30720u
#define HF_NSTAGE 3
#define HF_SMEM (HF_NSTAGE*HF_STAGE)

__device__ __forceinline__ void hf_load_stage(uint32_t sb, int stage,
    const __half* __restrict__ A, const __half* __restrict__ Bm,
    int lda, int ldb, int m0, int n0, int k0, int tid)
{
    uint32_t st = sb + (uint32_t)stage * HF_STAGE;
    #pragma unroll
    for (int it = 0; it < 6; it++) {
        int g = tid + it * 256;
        const __half* src;
        uint32_t dst;
        if (g < 512) {
            int r = g >> 2, q = g & 3;
            src = A + (long long)(m0 + r) * lda + k0 + q * 8;
            dst = st + HF_OFF_A + (uint32_t)(r * PITCH + q * 16);
        } else {
            int gb = g - 512;
            int r = gb >> 2, q = gb & 3;
            src = Bm + (long long)(n0 + r) * ldb + k0 + q * 8;
            dst = st + HF_OFF_B + (uint32_t)(r * PITCH + q * 16);
        }
        cpasync16(dst, src);
    }
}

__device__ __forceinline__ void hf_compute(uint32_t sb, int stage,
                                           int wm, int wn, int lane,
                                           float acc[2][16][4])
{
    uint32_t st = sb + (uint32_t)stage * HF_STAGE;
    uint32_t aBase = st + HF_OFF_A + (uint32_t)(wm * 32) * PITCH;
    uint32_t bBase = st + HF_OFF_B + (uint32_t)(wn * 128) * PITCH;
    int l15 = lane & 15;
    int lh = lane >> 4;
    int bn_off = ((lane >> 4) & 1) * 8 + (lane & 7);
    int bhalf = (lane >> 3) & 1;

    #pragma unroll
    for (int s = 0; s < 2; s++) {
        uint32_t aoff = (uint32_t)(s * 32 + lh * 16);
        uint32_t aF[2][4];
        ldsm4(aF[0], aBase + (uint32_t)(l15) * PITCH + aoff);
        ldsm4(aF[1], aBase + (uint32_t)(16 + l15) * PITCH + aoff);

        #pragma unroll
        for (int h = 0; h < 2; h++) {
            uint32_t bF[8][2];
            #pragma unroll
            for (int p = 0; p < 4; p++) {
                uint32_t addr = (uint32_t)(((h * 4 + p) * 16 + bn_off) * PITCH + s * 32 + bhalf * 16);
                uint32_t r4[4];
                ldsm4(r4, bBase + addr);
                bF[2*p][0] = r4[0]; bF[2*p][1] = r4[1];
                bF[2*p+1][0] = r4[2]; bF[2*p+1][1] = r4[3];
            }
            #pragma unroll
            for (int mt = 0; mt < 2; mt++)
                #pragma unroll
                for (int nt = 0; nt < 8; nt++)
                    mma_hf(acc[mt][h*8+nt], aF[mt], bF[nt]);
        }
    }
}

template<int OUTMODE>
__global__ void __launch_bounds__(256, 2)
gemm_hf(const __half* __restrict__ A, long long a_bs, int lda,
        const __half* __restrict__ Bm, long long b_bs, int ldb,
        float* __restrict__ Cf, __half* __restrict__ Ch,
        long long c_bs, int ldc,
        int K, const float* __restrict__ bias, int bias_mode, long long zstride)
{
    extern __shared__ char sm[];
    uint32_t sb = smem_u32(sm);
    int tid = threadIdx.x;
    int wid = tid >> 5, lane = tid & 31;
    int wm = wid & 3, wn = wid >> 2;
    int z = blockIdx.z;
    int m0 = blockIdx.y * 128;
    int n0 = blockIdx.x * 256;

    const __half* pA = A + (long long)z * a_bs;
    const __half* pB = Bm + (long long)z * b_bs;

    float acc[2][16][4] = {};
    int nc = K / 32;

    hf_load_stage(sb, 0, pA, pB, lda, ldb, m0, n0, 0, tid);
    asm volatile("cp.async.commit_group;" ::: "memory");
    if (nc > 1)
        hf_load_stage(sb, 1, pA, pB, lda, ldb, m0, n0, 32, tid);
    asm volatile("cp.async.commit_group;" ::: "memory");

    int stage = 0, nstage = 2 % HF_NSTAGE;
    for (int i = 0; i < nc; i++) {
        asm volatile("cp.async.wait_group 1;" ::: "memory");
        __syncthreads();
        if (i + 2 < nc)
            hf_load_stage(sb, nstage, pA, pB, lda, ldb, m0, n0, (i + 2) * 32, tid);
        asm volatile("cp.async.commit_group;" ::: "memory");
        hf_compute(sb, stage, wm, wn, lane, acc);
        stage = (stage + 1 == HF_NSTAGE) ? 0 : stage + 1;
        nstage = (nstage + 1 == HF_NSTAGE) ? 0 : nstage + 1;
    }

    int r = lane >> 2, cg = lane & 3;
    int mb = m0 + wm * 32, nb = n0 + wn * 128;
    const float* zb = bias + ((bias_mode >= 3) ? (long long)z * zstride : 0);
    #pragma unroll
    for (int mt = 0; mt < 2; mt++) {
        int mrow = mb + mt * 16 + r;
        float br0 = 0.0f, br1 = 0.0f;
        if (bias_mode == 1) { br0 = __ldg(&bias[mrow]); br1 = __ldg(&bias[mrow + 8]); }
        if (bias_mode == 4) { br0 = __ldg(&zb[mrow]);   br1 = __ldg(&zb[mrow + 8]); }
        #pragma unroll
        for (int nt = 0; nt < 16; nt++) {
            int col = nb + nt * 8 + cg * 2;
            float bc0 = 0.0f, bc1 = 0.0f;
            if (bias_mode == 2 || bias_mode == 3) { bc0 = __ldg(&zb[col]); bc1 = __ldg(&zb[col + 1]); }
            float v00 = acc[mt][nt][0] + br0 + bc0;
            float v01 = acc[mt][nt][1] + br0 + bc1;
            float v10 = acc[mt][nt][2] + br1 + bc0;
            float v11 = acc[mt][nt][3] + br1 + bc1;
            long long o0 = (long long)z * c_bs + (long long)mrow * ldc + col;
            long long o1 = o0 + (long long)8 * ldc;
            if (OUTMODE == 0) {
                *reinterpret_cast<float2*>(Cf + o0) = make_float2(v00, v01);
                *reinterpret_cast<float2*>(Cf + o1) = make_float2(v10, v11);
            } else {
                *reinterpret_cast<uint32_t*>(Ch + o0) = pack_h2(v00, v01);
                *reinterpret_cast<uint32_t*>(Ch + o1) = pack_h2(v10, v11);
            }
        }
    }
}

// ======================= setup / conversions =======================
// converts all weights AND zeroes the small accumulators
__global__ void convert_all_kernel(const float* __restrict__ a, const float* __restrict__ b,
                                   const float* __restrict__ c, const float* __restrict__ d,
                                   const float* __restrict__ bth_in,
                                   __half* oa, __half* ob, __half* oc, __half* od,
                                   float* obth, int n, float scale,
                                   float* pxsum, float* psum, float* bnpart) {
    int i = blockIdx.x * blockDim.x + threadIdx.x;
    if (i < n) {
        oa[i] = __float2half_rn(a[i] * scale);
        ob[i] = __float2half_rn(b[i]);
        oc[i] = __float2half_rn(c[i]);
        od[i] = __float2half_rn(d[i]);
    }
    if (i < CI_) obth[i] = bth_in[i] * scale;
    if (i < B_ * C_) pxsum[i] = 0.0f;
    if (i < B_ * M_) psum[i] = 0.0f;
    if (i < B_ * 2 * C_) bnpart[i] = 0.0f;
}

// src [z][R][CC] -> dst [z][CC][R] fp16
__global__ void transpose_convert_kernel(const float* __restrict__ src,
                                         __half* __restrict__ dst, int R, int CC) {
    __shared__ float tile[32][33];
    int z = blockIdx.z;
    int c0 = blockIdx.x * 32;
    int r0 = blockIdx.y * 32;
    int tx = threadIdx.x, ty = threadIdx.y;
    const float* s = src + (long long)z * R * CC;
    #pragma unroll
    for (int i = 0; i < 4; i++)
        tile[ty + i * 8][tx] = s[(long long)(r0 + ty + i * 8) * CC + c0 + tx];
    __syncthreads();
    __half* o = dst + (long long)z * R * CC;
    #pragma unroll
    for (int i = 0; i < 4; i++)
        o[(long long)(c0 + ty + i * 8) * R + r0 + tx] = __float2half_rn(tile[tx][ty + i * 8]);
}

// x [z][C][64x64] -> pooled transposed fp16 [z][m][c] ; also pxsum[z][c]
__global__ void pool_transpose_kernel(const float* __restrict__ x, __half* __restrict__ dst,
                                      float* __restrict__ pxsum) {
    __shared__ float tile[32][33];   // [c_local][m_local]
    int z = blockIdx.z;
    int m0 = blockIdx.x * 32;
    int c0 = blockIdx.y * 32;
    int tx = threadIdx.x, ty = threadIdx.y;
    #pragma unroll
    for (int i = 0; i < 4; i++) {
        int c = c0 + ty + i * 8;
        int m = m0 + tx;
        int pi = m >> 5, pj = m & 31;
        const float* b = x + ((long long)z * C_ + c) * 4096 + (pi * 2) * 64 + pj * 2;
        tile[ty + i * 8][tx] = fmaxf(fmaxf(b[0], b[1]), fmaxf(b[64], b[65]));
    }
    __syncthreads();
    #pragma unroll
    for (int i = 0; i < 4; i++)
        dst[((long long)z * M_ + m0 + ty + i * 8) * C_ + c0 + tx] =
            __float2half_rn(tile[tx][ty + i * 8]);
    if (ty == 0) {
        float s = 0.0f;
        #pragma unroll
        for (int mm = 0; mm < 32; mm++) s += tile[tx][mm];
        atomicAdd(&pxsum[z * C_ + c0 + tx], s);
    }
}

// gbias[z][ci] = -(w_g.pxsum)/M ; gmeanZ[z][ci] = (w_g.pxsum)/M + b_g
__global__ void gprep_kernel(const float* __restrict__ wg, const float* __restrict__ pxsum,
                             const float* __restrict__ b_g,
                             float* __restrict__ gbias, float* __restrict__ gmeanZ) {
    int ci = blockIdx.x, z = blockIdx.y, tid = threadIdx.x;
    const float* w = wg + (size_t)ci * C_;
    const float* ps = pxsum + z * C_;
    float s = 0.0f;
    for (int c = tid; c < C_; c += 256) s += w[c] * ps[c];
    __shared__ float red[8];
    #pragma unroll
    for (int o = 16; o > 0; o >>= 1) s += __shfl_xor_sync(0xffffffffu, s, o);
    if ((tid & 31) == 0) red[tid >> 5] = s;
    __syncthreads();
    if (tid == 0) {
        float tot = (red[0] + red[1]) + (red[2] + red[3]) + (red[4] + red[5]) + (red[6] + red[7]);
        float gm = tot * (1.0f / M_);
        gbias[z * CI_ + ci] = -gm;
        gmeanZ[z * CI_ + ci] = gm + b_g[ci];
    }
}

// ======================= softmax (16 rows/block) + fused psum =======================
__global__ void softmax_psum_kernel(const __half* __restrict__ s, __half* __restrict__ p,
                                    float* __restrict__ psum) {
    int z = blockIdx.y;
    int n0 = blockIdx.x * 16;
    int tid = threadIdx.x;
    __shared__ float pl[1024];
    __shared__ float red[8], red2[8];
    #pragma unroll
    for (int i = 0; i < 4; i++) pl[tid + i * 256] = 0.0f;
    __syncthreads();

    for (int rr = 0; rr < 16; rr++) {
        const __half* row = s + ((size_t)z * N_ + n0 + rr) * M_;
        float v[4];
        float mx = -1e30f;
        #pragma unroll
        for (int i = 0; i < 4; i++) { v[i] = __half2float(row[tid + 256 * i]); mx = fmaxf(mx, v[i]); }
        #pragma unroll
        for (int o = 16; o > 0; o >>= 1) mx = fmaxf(mx, __shfl_xor_sync(0xffffffffu, mx, o));
        if ((tid & 31) == 0) red[tid >> 5] = mx;
        __syncthreads();
        mx = fmaxf(fmaxf(fmaxf(red[0], red[1]), fmaxf(red[2], red[3])),
                   fmaxf(fmaxf(red[4], red[5]), fmaxf(red[6], red[7])));
        float sum = 0.0f;
        #pragma unroll
        for (int i = 0; i < 4; i++) { v[i] = __expf(v[i] - mx); sum += v[i]; }
        #pragma unroll
        for (int o = 16; o > 0; o >>= 1) sum += __shfl_xor_sync(0xffffffffu, sum, o);
        if ((tid & 31) == 0) red2[tid >> 5] = sum;
        __syncthreads();
        sum = (red2[0] + red2[1]) + (red2[2] + red2[3]) + (red2[4] + red2[5]) + (red2[6] + red2[7]);
        float inv = 1.0f / sum;
        __half* prow = p + ((size_t)z * N_ + n0 + rr) * M_;
        #pragma unroll
        for (int i = 0; i < 4; i++) {
            float pv = v[i] * inv;
            prow[tid + 256 * i] = __float2half_rn(pv);
            pl[tid + i * 256] += pv;
        }
        __syncthreads();
    }
    #pragma unroll
    for (int i = 0; i < 4; i++)
        atomicAdd(&psum[z * M_ + tid + i * 256], pl[tid + i * 256]);
}

// negtq[z][ci] = -(1/N) sum_m psum[z][m]*gdev[z][ci][m] ; tmean = tq + gmeanZ
__global__ void tq_kernel(const __half* __restrict__ gdev, const float* __restrict__ psum,
                          const float* __restrict__ gmeanZ,
                          float* __restrict__ negtq, float* __restrict__ tmean) {
    int ci = blockIdx.x, z = blockIdx.y, tid = threadIdx.x;
    const __half* g = gdev + ((size_t)z * CI_ + ci) * M_;
    const float* ps = psum + z * M_;
    float s = 0.0f;
    for (int m = tid; m < M_; m += 256) s += __half2float(g[m]) * ps[m];
    __shared__ float red[8];
    #pragma unroll
    for (int o = 16; o > 0; o >>= 1) s += __shfl_xor_sync(0xffffffffu, s, o);
    if ((tid & 31) == 0) red[tid >> 5] = s;
    __syncthreads();
    if (tid == 0) {
        float tot = (red[0] + red[1]) + (red[2] + red[3]) + (red[4] + red[5]) + (red[6] + red[7]);
        float tq = tot * (1.0f / N_);
        negtq[z * CI_ + ci] = -tq;
        tmean[z * CI_ + ci] = tq + gmeanZ[z * CI_ + ci];
    }
}

__global__ void ymean_kernel(const float* __restrict__ w_out, const float* __restrict__ b_out,
                             const float* __restrict__ tmean, float* __restrict__ ymean) {
    int c = blockIdx.x * 256 + threadIdx.x;
    int z = blockIdx.y;
    const float* w = w_out + (long long)c * CI_;
    const float* tm = tmean + z * CI_;
    float s = b_out[c];
    #pragma unroll 4
    for (int ci = 0; ci < CI_; ci++)
        s += w[ci] * tm[ci];
    ymean[z * C_ + c] = s;
}

// ======================= BatchNorm =======================
__global__ void bn_stats_kernel(const __half* __restrict__ ydev, float* __restrict__ part) {
    int c = blockIdx.x * 128 + threadIdx.x;
    int z = blockIdx.y;
    int n0 = blockIdx.z * 512;
    const __half* base = ydev + ((long long)z * N_ + n0) * C_ + c;
    float s = 0.0f, s2 = 0.0f;
    for (int r = 0; r < 512; r++) {
        float v = __half2float(base[(long long)r * C_]);
        s += v; s2 += v * v;
    }
    atomicAdd(&part[(long long)z * 2 * C_ + c], s);
    atomicAdd(&part[(long long)z * 2 * C_ + C_ + c], s2);
}
__global__ void bn_final_kernel(const float* __restrict__ part, const float* __restrict__ ymean,
                                float* __restrict__ stat) {
    int c = blockIdx.x * blockDim.x + threadIdx.x;
    if (c >= C_) return;
    double sum = 0.0, sq = 0.0;
    #pragma unroll
    for (int z = 0; z < B_; z++) {
        double s1 = (double)part[(long long)z * 2 * C_ + c];
        double s2 = (double)part[(long long)z * 2 * C_ + C_ + c];
        double ym = (double)ymean[z * C_ + c];
        sum += s1 + (double)N_ * ym;
        sq  += s2 + 2.0 * ym * s1 + (double)N_ * ym * ym;
    }
    double cnt = (double)B_ * N_;
    double mean = sum / cnt;
    double var = sq / cnt - mean * mean;
    stat[c] = (float)mean;
    stat[C_ + c] = rsqrtf((float)var + 1e-5f);
}
__global__ void bn_apply_kernel(const __half* __restrict__ ydev, const float* __restrict__ x,
                                const float* __restrict__ stat, const float* __restrict__ ymean,
                                const float* __restrict__ gamma, const float* __restrict__ beta,
                                float* __restrict__ out) {
    __shared__ float tile[32][33];
    int z = blockIdx.z;
    int n0 = blockIdx.x * 32;
    int c0 = blockIdx.y * 32;
    int tx = threadIdx.x, ty = threadIdx.y;
    #pragma unroll
    for (int i = 0; i < 4; i++)
        tile[ty + i * 8][tx] =
            __half2float(ydev[((long long)z * N_ + n0 + ty + i * 8) * C_ + c0 + tx]);
    __syncthreads();
    #pragma unroll
    for (int i = 0; i < 4; i++) {
        int c = c0 + ty + i * 8;
        int n = n0 + tx;
        float mean = stat[c], rstd = stat[C_ + c];
        float ym = ymean[z * C_ + c];
        long long o = ((long long)z * C_ + c) * N_ + n;
        out[o] = (tile[tx][ty + i * 8] + ym - mean) * rstd * gamma[c] + beta[c] + x[o];
    }
}

// ======================= launch =======================
extern "C" void kernel_launch(void* const* d_in, const int* in_sizes, int n_in,
                              void* d_out, int out_size) {
    const float* x       = (const float*)d_in[0];
    const float* w_theta = (const float*)d_in[1];
    const float* b_theta = (const float*)d_in[2];
    const float* w_phi   = (const float*)d_in[3];
    const float* b_phi   = (const float*)d_in[4];
    const float* w_g     = (const float*)d_in[5];
    const float* b_g     = (const float*)d_in[6];
    const float* w_out   = (const float*)d_in[7];
    const float* b_out   = (const float*)d_in[8];
    const float* gamma   = (const float*)d_in[9];
    const float* beta    = (const float*)d_in[10];
    float* out = (float*)d_out;

    cudaFuncSetAttribute(gemm_hf<0>, cudaFuncAttributeMaxDynamicSharedMemorySize, HF_SMEM);
    cudaFuncSetAttribute(gemm_hf<1>, cudaFuncAttributeMaxDynamicSharedMemorySize, HF_SMEM);

    __half *xT, *pxT, *wth, *wph, *wg, *wo, *thT, *phT, *gdev, *scoresh, *p, *tdev, *ydev;
    float *bth, *pxsum, *psum, *gbias, *gmeanZ, *negtq, *tmean, *ymean, *bnpart, *bnstat;
    cudaGetSymbolAddress((void**)&xT, s_xT);
    cudaGetSymbolAddress((void**)&pxT, s_pxT);
    cudaGetSymbolAddress((void**)&wth, s_wth);
    cudaGetSymbolAddress((void**)&wph, s_wph);
    cudaGetSymbolAddress((void**)&wg, s_wg);
    cudaGetSymbolAddress((void**)&wo, s_wo);
    cudaGetSymbolAddress((void**)&bth, s_bth);
    cudaGetSymbolAddress((void**)&thT, s_thT);
    cudaGetSymbolAddress((void**)&phT, s_phT);
    cudaGetSymbolAddress((void**)&gdev, s_gdev);
    cudaGetSymbolAddress((void**)&scoresh, s_scoresh);
    cudaGetSymbolAddress((void**)&p, s_p);
    cudaGetSymbolAddress((void**)&tdev, s_tdev);
    cudaGetSymbolAddress((void**)&pxsum, s_pxsum);
    cudaGetSymbolAddress((void**)&psum, s_psum);
    cudaGetSymbolAddress((void**)&gbias, s_gbias);
    cudaGetSymbolAddress((void**)&gmeanZ, s_gmeanZ);
    cudaGetSymbolAddress((void**)&negtq, s_negtq);
    cudaGetSymbolAddress((void**)&tmean, s_tmean);
    cudaGetSymbolAddress((void**)&ymean, s_ymean);
    cudaGetSymbolAddress((void**)&ydev, s_ydev);
    cudaGetSymbolAddress((void**)&bnpart, s_bnpart);
    cudaGetSymbolAddress((void**)&bnstat, s_bnstat);

    dim3 tb(32, 8);
    float scale = rsqrtf((float)CI_);

    // launch #1: converts + zeroing
    convert_all_kernel<<<(CI_ * C_ + 255) / 256, 256>>>(
        w_theta, w_phi, w_g, w_out, b_theta, wth, wph, wg, wo, bth, CI_ * C_, scale,
        pxsum, psum, bnpart);
    // #2, #3
    transpose_convert_kernel<<<dim3(N_ / 32, C_ / 32, B_), tb>>>(x, xT, C_, N_);
    pool_transpose_kernel<<<dim3(M_ / 32, C_ / 32, B_), tb>>>(x, pxT, pxsum);

    // #4 = GEMM1 (profiled by ncu): thT[n][ci] = xT @ (s*w_theta)^T + s*b_theta
    gemm_hf<1><<<dim3(CI_ / 256, N_ / 128, B_), 256, HF_SMEM>>>(
        xT, (long long)N_ * C_, C_,
        wth, 0, C_,
        nullptr, thT, (long long)N_ * CI_, CI_,
        C_, bth, 2, 0);
    // #5 gprep (needs pool only)
    gprep_kernel<<<dim3(CI_, B_), 256>>>(w_g, pxsum, b_g, gbias, gmeanZ);
    // GEMM2 (fp16): phT[m][ci]
    gemm_hf<1><<<dim3(CI_ / 256, M_ / 128, B_), 256, HF_SMEM>>>(
        pxT, (long long)M_ * C_, C_,
        wph, 0, C_,
        nullptr, phT, (long long)M_ * CI_, CI_,
        C_, b_phi, 2, 0);
    // GEMM3 (fp16 -> centered gdev fp16)
    gemm_hf<1><<<dim3(M_ / 256, CI_ / 128, B_), 256, HF_SMEM>>>(
        wg, 0, C_,
        pxT, (long long)M_ * C_, C_,
        nullptr, gdev, (long long)CI_ * M_, M_,
        C_, gbias, 4, CI_);
    // GEMM4 (fp16 -> fp16): pre-scaled scores
    gemm_hf<1><<<dim3(M_ / 256, N_ / 128, B_), 256, HF_SMEM>>>(
        thT, (long long)N_ * CI_, CI_,
        phT, (long long)M_ * CI_, CI_,
        nullptr, scoresh, (long long)N_ * M_, M_,
        CI_, nullptr, 0, 0);
    softmax_psum_kernel<<<dim3(N_ / 16, B_), 256>>>(scoresh, p, psum);
    tq_kernel<<<dim3(CI_, B_), 256>>>(gdev, psum, gmeanZ, negtq, tmean);
    // GEMM5 (fp16 -> tdev fp16)
    gemm_hf<1><<<dim3(CI_ / 256, N_ / 128, B_), 256, HF_SMEM>>>(
        p, (long long)N_ * M_, M_,
        gdev, (long long)CI_ * M_, M_,
        nullptr, tdev, (long long)N_ * CI_, CI_,
        M_, negtq, 3, CI_);
    ymean_kernel<<<dim3(C_ / 256, B_), 256>>>(w_out, b_out, tmean, ymean);
    // GEMM6 (fp16 -> fp16): ydev
    gemm_hf<1><<<dim3(C_ / 256, N_ / 128, B_), 256, HF_SMEM>>>(
        tdev, (long long)N_ * CI_, CI_,
        wo, 0, CI_,
        nullptr, ydev, (long long)N_ * C_, C_,
        CI_, nullptr, 0, 0);

    bn_stats_kernel<<<dim3(C_ / 128, B_, 8), 128>>>(ydev, bnpart);
    bn_final_kernel<<<4, 256>>>(bnpart, ymean, bnstat);
    bn_apply_kernel<<<dim3(N_ / 32, C_ / 32, B_), tb>>>(ydev, x, bnstat, ymean, gamma, beta, out);
}

// round 17
// speedup vs baseline: 1.4389x; 1.4389x over previous
#include <cuda_runtime.h>
#include <cuda_fp16.h>
#include <cstdint>
#include <math.h>

#define B_  8
#define C_  1024
#define CI_ 512
#define N_  4096
#define M_  1024

// ======================= scratch (device globals) =======================
__device__ __align__(1024) __half s_xT[(size_t)B_*N_*C_];     // [b][n][c]
__device__ __align__(1024) __half s_pxT[(size_t)B_*M_*C_];    // [b][m][c]
__device__ __align__(1024) __half s_wth[CI_*C_];              // scaled by Ci^-0.5
__device__ __align__(1024) __half s_wph[CI_*C_];
__device__ __align__(1024) __half s_wg[CI_*C_];
__device__ __align__(1024) __half s_wo[C_*CI_];
__device__ __align__(1024) float  s_bth[CI_];                 // scaled b_theta
__device__ __align__(1024) __half s_thT[(size_t)B_*N_*CI_];   // [b][n][ci]
__device__ __align__(1024) __half s_phT[(size_t)B_*M_*CI_];   // [b][m][ci]
__device__ __align__(1024) __half s_gdev[(size_t)B_*CI_*M_];  // centered g fp16
__device__ __align__(1024) __half s_scoresh[(size_t)B_*N_*M_];// fp16 pre-scaled scores
__device__ __align__(1024) __half s_p[(size_t)B_*N_*M_];
__device__ __align__(1024) __half s_tdev[(size_t)B_*N_*CI_];
__device__ __align__(1024) float  s_pxsum[B_*C_];
__device__ __align__(1024) float  s_psum[B_*M_];
__device__ __align__(1024) float  s_gbias[B_*CI_];            // -(w_g.pxsum)/M
__device__ __align__(1024) float  s_gmeanZ[B_*CI_];           // (w_g.pxsum)/M + b_g
__device__ __align__(1024) float  s_negtq[B_*CI_];
__device__ __align__(1024) float  s_tmean[B_*CI_];
__device__ __align__(1024) float  s_ymean[B_*C_];
__device__ __align__(1024) __half s_ydev[(size_t)B_*N_*C_];   // fp16 ydev
__device__ __align__(1024) float  s_bnpart[B_*2*C_];          // per-z col sum/sumsq of ydev
__device__ float  s_bnstat[2*C_];

// ======================= helpers =======================
__device__ __forceinline__ uint32_t smem_u32(const void* p){
    uint32_t a;
    asm("{ .reg .u64 t; cvta.to.shared.u64 t, %1; cvt.u32.u64 %0, t; }" : "=r"(a) : "l"(p));
    return a;
}
__device__ __forceinline__ void cpasync16(uint32_t dst, const void* src){
    asm volatile("cp.async.cg.shared.global [%0], [%1], 16;" :: "r"(dst), "l"(src));
}
__device__ __forceinline__ void ldsm4(uint32_t* r, uint32_t addr){
    asm volatile("ldmatrix.sync.aligned.m8n8.x4.shared.b16 {%0,%1,%2,%3}, [%4];"
        : "=r"(r[0]), "=r"(r[1]), "=r"(r[2]), "=r"(r[3]) : "r"(addr));
}
__device__ __forceinline__ void mma_hf(float* c, const uint32_t* a, const uint32_t* b){
    asm volatile("mma.sync.aligned.m16n8k16.row.col.f32.f16.f16.f32 "
        "{%0,%1,%2,%3},{%4,%5,%6,%7},{%8,%9},{%0,%1,%2,%3};"
        : "+f"(c[0]), "+f"(c[1]), "+f"(c[2]), "+f"(c[3])
        : "r"(a[0]), "r"(a[1]), "r"(a[2]), "r"(a[3]), "r"(b[0]), "r"(b[1]));
}
__device__ __forceinline__ uint32_t pack_h2(float x, float y){
    __half2 t = __floats2half2_rn(x, y);
    return *reinterpret_cast<uint32_t*>(&t);
}

#define PITCH 80

// ======================= fp16 GEMM (R15 proven core: 4-stage, 1 CTA/SM) ==========
// D[m][n] = sum_k A[m][k]*B[n][k] (+bias). CTA 128x256, Kc=32, 8 warps.
// bias_mode: 0 none, 1 row, 2 col, 3 per-z col (bias[z*zs+col]), 4 per-z row.
// OUTMODE 0: fp32 ; 1: fp16
#define HF_OFF_A  0u
#define HF_OFF_B  10240u
#define HF_STAGE  30720u
#define HF_NSTAGE 4
#define HF_SMEM (HF_NSTAGE*HF_STAGE)

__device__ __forceinline__ void hf_load_stage(uint32_t sb, int stage,
    const __half* __restrict__ A, const __half* __restrict__ Bm,
    int lda, int ldb, int m0, int n0, int k0, int tid)
{
    uint32_t st = sb + (uint32_t)stage * HF_STAGE;
    #pragma unroll
    for (int it = 0; it < 6; it++) {
        int g = tid + it * 256;
        const __half* src;
        uint32_t dst;
        if (g < 512) {
            int r = g >> 2, q = g & 3;
            src = A + (long long)(m0 + r) * lda + k0 + q * 8;
            dst = st + HF_OFF_A + (uint32_t)(r * PITCH + q * 16);
        } else {
            int gb = g - 512;
            int r = gb >> 2, q = gb & 3;
            src = Bm + (long long)(n0 + r) * ldb + k0 + q * 8;
            dst = st + HF_OFF_B + (uint32_t)(r * PITCH + q * 16);
        }
        cpasync16(dst, src);
    }
}

__device__ __forceinline__ void hf_compute(uint32_t sb, int stage,
                                           int wm, int wn, int lane,
                                           float acc[2][16][4])
{
    uint32_t st = sb + (uint32_t)stage * HF_STAGE;
    uint32_t aBase = st + HF_OFF_A + (uint32_t)(wm * 32) * PITCH;
    uint32_t bBase = st + HF_OFF_B + (uint32_t)(wn * 128) * PITCH;
    int l15 = lane & 15;
    int lh = lane >> 4;
    int bn_off = ((lane >> 4) & 1) * 8 + (lane & 7);
    int bhalf = (lane >> 3) & 1;

    #pragma unroll
    for (int s = 0; s < 2; s++) {
        uint32_t aoff = (uint32_t)(s * 32 + lh * 16);
        uint32_t aF[2][4];
        ldsm4(aF[0], aBase + (uint32_t)(l15) * PITCH + aoff);
        ldsm4(aF[1], aBase + (uint32_t)(16 + l15) * PITCH + aoff);

        #pragma unroll
        for (int h = 0; h < 2; h++) {
            uint32_t bF[8][2];
            #pragma unroll
            for (int p = 0; p < 4; p++) {
                uint32_t addr = (uint32_t)(((h * 4 + p) * 16 + bn_off) * PITCH + s * 32 + bhalf * 16);
                uint32_t r4[4];
                ldsm4(r4, bBase + addr);
                bF[2*p][0] = r4[0]; bF[2*p][1] = r4[1];
                bF[2*p+1][0] = r4[2]; bF[2*p+1][1] = r4[3];
            }
            #pragma unroll
            for (int mt = 0; mt < 2; mt++)
                #pragma unroll
                for (int nt = 0; nt < 8; nt++)
                    mma_hf(acc[mt][h*8+nt], aF[mt], bF[nt]);
        }
    }
}

template<int OUTMODE>
__global__ void __launch_bounds__(256, 1)
gemm_hf(const __half* __restrict__ A, long long a_bs, int lda,
        const __half* __restrict__ Bm, long long b_bs, int ldb,
        float* __restrict__ Cf, __half* __restrict__ Ch,
        long long c_bs, int ldc,
        int K, const float* __restrict__ bias, int bias_mode, long long zstride)
{
    extern __shared__ char sm[];
    uint32_t sb = smem_u32(sm);
    int tid = threadIdx.x;
    int wid = tid >> 5, lane = tid & 31;
    int wm = wid & 3, wn = wid >> 2;
    int z = blockIdx.z;
    int m0 = blockIdx.y * 128;
    int n0 = blockIdx.x * 256;

    const __half* pA = A + (long long)z * a_bs;
    const __half* pB = Bm + (long long)z * b_bs;

    float acc[2][16][4] = {};
    int nc = K / 32;

    #pragma unroll
    for (int s = 0; s < 3; s++) {
        if (s < nc)
            hf_load_stage(sb, s, pA, pB, lda, ldb, m0, n0, s * 32, tid);
        asm volatile("cp.async.commit_group;" ::: "memory");
    }

    for (int i = 0; i < nc; i++) {
        asm volatile("cp.async.wait_group 2;" ::: "memory");
        __syncthreads();
        if (i + 3 < nc)
            hf_load_stage(sb, (i + 3) & (HF_NSTAGE - 1), pA, pB, lda, ldb, m0, n0, (i + 3) * 32, tid);
        asm volatile("cp.async.commit_group;" ::: "memory");
        hf_compute(sb, i & (HF_NSTAGE - 1), wm, wn, lane, acc);
    }

    int r = lane >> 2, cg = lane & 3;
    int mb = m0 + wm * 32, nb = n0 + wn * 128;
    const float* zb = bias + ((bias_mode >= 3) ? (long long)z * zstride : 0);
    #pragma unroll
    for (int mt = 0; mt < 2; mt++) {
        int mrow = mb + mt * 16 + r;
        float br0 = 0.0f, br1 = 0.0f;
        if (bias_mode == 1) { br0 = __ldg(&bias[mrow]); br1 = __ldg(&bias[mrow + 8]); }
        if (bias_mode == 4) { br0 = __ldg(&zb[mrow]);   br1 = __ldg(&zb[mrow + 8]); }
        #pragma unroll
        for (int nt = 0; nt < 16; nt++) {
            int col = nb + nt * 8 + cg * 2;
            float bc0 = 0.0f, bc1 = 0.0f;
            if (bias_mode == 2 || bias_mode == 3) { bc0 = __ldg(&zb[col]); bc1 = __ldg(&zb[col + 1]); }
            float v00 = acc[mt][nt][0] + br0 + bc0;
            float v01 = acc[mt][nt][1] + br0 + bc1;
            float v10 = acc[mt][nt][2] + br1 + bc0;
            float v11 = acc[mt][nt][3] + br1 + bc1;
            long long o0 = (long long)z * c_bs + (long long)mrow * ldc + col;
            long long o1 = o0 + (long long)8 * ldc;
            if (OUTMODE == 0) {
                *reinterpret_cast<float2*>(Cf + o0) = make_float2(v00, v01);
                *reinterpret_cast<float2*>(Cf + o1) = make_float2(v10, v11);
            } else {
                *reinterpret_cast<uint32_t*>(Ch + o0) = pack_h2(v00, v01);
                *reinterpret_cast<uint32_t*>(Ch + o1) = pack_h2(v10, v11);
            }
        }
    }
}

// ======================= setup / conversions =======================
__global__ void convert_all_kernel(const float* __restrict__ a, const float* __restrict__ b,
                                   const float* __restrict__ c, const float* __restrict__ d,
                                   const float* __restrict__ bth_in,
                                   __half* oa, __half* ob, __half* oc, __half* od,
                                   float* obth, int n, float scale,
                                   float* pxsum, float* psum, float* bnpart) {
    int i = blockIdx.x * blockDim.x + threadIdx.x;
    if (i < n) {
        oa[i] = __float2half_rn(a[i] * scale);
        ob[i] = __float2half_rn(b[i]);
        oc[i] = __float2half_rn(c[i]);
        od[i] = __float2half_rn(d[i]);
    }
    if (i < CI_) obth[i] = bth_in[i] * scale;
    if (i < B_ * C_) pxsum[i] = 0.0f;
    if (i < B_ * M_) psum[i] = 0.0f;
    if (i < B_ * 2 * C_) bnpart[i] = 0.0f;
}

// src [z][R][CC] -> dst [z][CC][R] fp16
__global__ void transpose_convert_kernel(const float* __restrict__ src,
                                         __half* __restrict__ dst, int R, int CC) {
    __shared__ float tile[32][33];
    int z = blockIdx.z;
    int c0 = blockIdx.x * 32;
    int r0 = blockIdx.y * 32;
    int tx = threadIdx.x, ty = threadIdx.y;
    const float* s = src + (long long)z * R * CC;
    #pragma unroll
    for (int i = 0; i < 4; i++)
        tile[ty + i * 8][tx] = s[(long long)(r0 + ty + i * 8) * CC + c0 + tx];
    __syncthreads();
    __half* o = dst + (long long)z * R * CC;
    #pragma unroll
    for (int i = 0; i < 4; i++)
        o[(long long)(c0 + ty + i * 8) * R + r0 + tx] = __float2half_rn(tile[tx][ty + i * 8]);
}

// x [z][C][64x64] -> pooled transposed fp16 [z][m][c] ; also pxsum[z][c]
__global__ void pool_transpose_kernel(const float* __restrict__ x, __half* __restrict__ dst,
                                      float* __restrict__ pxsum) {
    __shared__ float tile[32][33];   // [c_local][m_local]
    int z = blockIdx.z;
    int m0 = blockIdx.x * 32;
    int c0 = blockIdx.y * 32;
    int tx = threadIdx.x, ty = threadIdx.y;
    #pragma unroll
    for (int i = 0; i < 4; i++) {
        int c = c0 + ty + i * 8;
        int m = m0 + tx;
        int pi = m >> 5, pj = m & 31;
        const float* b = x + ((long long)z * C_ + c) * 4096 + (pi * 2) * 64 + pj * 2;
        tile[ty + i * 8][tx] = fmaxf(fmaxf(b[0], b[1]), fmaxf(b[64], b[65]));
    }
    __syncthreads();
    #pragma unroll
    for (int i = 0; i < 4; i++)
        dst[((long long)z * M_ + m0 + ty + i * 8) * C_ + c0 + tx] =
            __float2half_rn(tile[tx][ty + i * 8]);
    if (ty == 0) {
        float s = 0.0f;
        #pragma unroll
        for (int mm = 0; mm < 32; mm++) s += tile[tx][mm];
        atomicAdd(&pxsum[z * C_ + c0 + tx], s);
    }
}

// gbias[z][ci] = -(w_g.pxsum)/M ; gmeanZ[z][ci] = (w_g.pxsum)/M + b_g
__global__ void gprep_kernel(const float* __restrict__ wg, const float* __restrict__ pxsum,
                             const float* __restrict__ b_g,
                             float* __restrict__ gbias, float* __restrict__ gmeanZ) {
    int ci = blockIdx.x, z = blockIdx.y, tid = threadIdx.x;
    const float* w = wg + (size_t)ci * C_;
    const float* ps = pxsum + z * C_;
    float s = 0.0f;
    for (int c = tid; c < C_; c += 256) s += w[c] * ps[c];
    __shared__ float red[8];
    #pragma unroll
    for (int o = 16; o > 0; o >>= 1) s += __shfl_xor_sync(0xffffffffu, s, o);
    if ((tid & 31) == 0) red[tid >> 5] = s;
    __syncthreads();
    if (tid == 0) {
        float tot = (red[0] + red[1]) + (red[2] + red[3]) + (red[4] + red[5]) + (red[6] + red[7]);
        float gm = tot * (1.0f / M_);
        gbias[z * CI_ + ci] = -gm;
        gmeanZ[z * CI_ + ci] = gm + b_g[ci];
    }
}

// ======================= softmax: warp-per-row + fused psum =======================
// 8 warps/block, each warp handles one row; no per-row block syncs.
__global__ void softmax_psum_kernel(const __half* __restrict__ s, __half* __restrict__ p,
                                    float* __restrict__ psum) {
    int z = blockIdx.y;
    int n = blockIdx.x * 8 + (threadIdx.x >> 5);
    int lane = threadIdx.x & 31;
    int tid = threadIdx.x;
    __shared__ float pl[1024];
    #pragma unroll
    for (int i = 0; i < 4; i++) pl[tid + i * 256] = 0.0f;
    __syncthreads();

    const __half* row = s + ((size_t)z * N_ + n) * M_;
    float v[32];
    float mx = -1e30f;
    #pragma unroll
    for (int j = 0; j < 32; j++) {
        v[j] = __half2float(row[lane + 32 * j]);
        mx = fmaxf(mx, v[j]);
    }
    #pragma unroll
    for (int o = 16; o > 0; o >>= 1) mx = fmaxf(mx, __shfl_xor_sync(0xffffffffu, mx, o));
    float sum = 0.0f;
    #pragma unroll
    for (int j = 0; j < 32; j++) { v[j] = __expf(v[j] - mx); sum += v[j]; }
    #pragma unroll
    for (int o = 16; o > 0; o >>= 1) sum += __shfl_xor_sync(0xffffffffu, sum, o);
    float inv = 1.0f / sum;
    __half* prow = p + ((size_t)z * N_ + n) * M_;
    #pragma unroll
    for (int j = 0; j < 32; j++) {
        float pv = v[j] * inv;
        prow[lane + 32 * j] = __float2half_rn(pv);
        atomicAdd(&pl[lane + 32 * j], pv);
    }
    __syncthreads();
    #pragma unroll
    for (int i = 0; i < 4; i++)
        atomicAdd(&psum[z * M_ + tid + i * 256], pl[tid + i * 256]);
}

// negtq[z][ci] = -(1/N) sum_m psum[z][m]*gdev[z][ci][m] ; tmean = tq + gmeanZ
__global__ void tq_kernel(const __half* __restrict__ gdev, const float* __restrict__ psum,
                          const float* __restrict__ gmeanZ,
                          float* __restrict__ negtq, float* __restrict__ tmean) {
    int ci = blockIdx.x, z = blockIdx.y, tid = threadIdx.x;
    const __half* g = gdev + ((size_t)z * CI_ + ci) * M_;
    const float* ps = psum + z * M_;
    float s = 0.0f;
    for (int m = tid; m < M_; m += 256) s += __half2float(g[m]) * ps[m];
    __shared__ float red[8];
    #pragma unroll
    for (int o = 16; o > 0; o >>= 1) s += __shfl_xor_sync(0xffffffffu, s, o);
    if ((tid & 31) == 0) red[tid >> 5] = s;
    __syncthreads();
    if (tid == 0) {
        float tot = (red[0] + red[1]) + (red[2] + red[3]) + (red[4] + red[5]) + (red[6] + red[7]);
        float tq = tot * (1.0f / N_);
        negtq[z * CI_ + ci] = -tq;
        tmean[z * CI_ + ci] = tq + gmeanZ[z * CI_ + ci];
    }
}

__global__ void ymean_kernel(const float* __restrict__ w_out, const float* __restrict__ b_out,
                             const float* __restrict__ tmean, float* __restrict__ ymean) {
    int c = blockIdx.x * 256 + threadIdx.x;
    int z = blockIdx.y;
    const float* w = w_out + (long long)c * CI_;
    const float* tm = tmean + z * CI_;
    float s = b_out[c];
    #pragma unroll 4
    for (int ci = 0; ci < CI_; ci++)
        s += w[ci] * tm[ci];
    ymean[z * C_ + c] = s;
}

// ======================= BatchNorm =======================
__global__ void bn_stats_kernel(const __half* __restrict__ ydev, float* __restrict__ part) {
    int c = blockIdx.x * 128 + threadIdx.x;
    int z = blockIdx.y;
    int n0 = blockIdx.z * 512;
    const __half* base = ydev + ((long long)z * N_ + n0) * C_ + c;
    float s = 0.0f, s2 = 0.0f;
    for (int r = 0; r < 512; r++) {
        float v = __half2float(base[(long long)r * C_]);
        s += v; s2 += v * v;
    }
    atomicAdd(&part[(long long)z * 2 * C_ + c], s);
    atomicAdd(&part[(long long)z * 2 * C_ + C_ + c], s2);
}
__global__ void bn_final_kernel(const float* __restrict__ part, const float* __restrict__ ymean,
                                float* __restrict__ stat) {
    int c = blockIdx.x * blockDim.x + threadIdx.x;
    if (c >= C_) return;
    double sum = 0.0, sq = 0.0;
    #pragma unroll
    for (int z = 0; z < B_; z++) {
        double s1 = (double)part[(long long)z * 2 * C_ + c];
        double s2 = (double)part[(long long)z * 2 * C_ + C_ + c];
        double ym = (double)ymean[z * C_ + c];
        sum += s1 + (double)N_ * ym;
        sq  += s2 + 2.0 * ym * s1 + (double)N_ * ym * ym;
    }
    double cnt = (double)B_ * N_;
    double mean = sum / cnt;
    double var = sq / cnt - mean * mean;
    stat[c] = (float)mean;
    stat[C_ + c] = rsqrtf((float)var + 1e-5f);
}
__global__ void bn_apply_kernel(const __half* __restrict__ ydev, const float* __restrict__ x,
                                const float* __restrict__ stat, const float* __restrict__ ymean,
                                const float* __restrict__ gamma, const float* __restrict__ beta,
                                float* __restrict__ out) {
    __shared__ float tile[32][33];
    int z = blockIdx.z;
    int n0 = blockIdx.x * 32;
    int c0 = blockIdx.y * 32;
    int tx = threadIdx.x, ty = threadIdx.y;
    #pragma unroll
    for (int i = 0; i < 4; i++)
        tile[ty + i * 8][tx] =
            __half2float(ydev[((long long)z * N_ + n0 + ty + i * 8) * C_ + c0 + tx]);
    __syncthreads();
    #pragma unroll
    for (int i = 0; i < 4; i++) {
        int c = c0 + ty + i * 8;
        int n = n0 + tx;
        float mean = stat[c], rstd = stat[C_ + c];
        float ym = ymean[z * C_ + c];
        long long o = ((long long)z * C_ + c) * N_ + n;
        out[o] = (tile[tx][ty + i * 8] + ym - mean) * rstd * gamma[c] + beta[c] + x[o];
    }
}

// ======================= launch =======================
extern "C" void kernel_launch(void* const* d_in, const int* in_sizes, int n_in,
                              void* d_out, int out_size) {
    const float* x       = (const float*)d_in[0];
    const float* w_theta = (const float*)d_in[1];
    const float* b_theta = (const float*)d_in[2];
    const float* w_phi   = (const float*)d_in[3];
    const float* b_phi   = (const float*)d_in[4];
    const float* w_g     = (const float*)d_in[5];
    const float* b_g     = (const float*)d_in[6];
    const float* w_out   = (const float*)d_in[7];
    const float* b_out   = (const float*)d_in[8];
    const float* gamma   = (const float*)d_in[9];
    const float* beta    = (const float*)d_in[10];
    float* out = (float*)d_out;

    cudaFuncSetAttribute(gemm_hf<0>, cudaFuncAttributeMaxDynamicSharedMemorySize, HF_SMEM);
    cudaFuncSetAttribute(gemm_hf<1>, cudaFuncAttributeMaxDynamicSharedMemorySize, HF_SMEM);

    __half *xT, *pxT, *wth, *wph, *wg, *wo, *thT, *phT, *gdev, *scoresh, *p, *tdev, *ydev;
    float *bth, *pxsum, *psum, *gbias, *gmeanZ, *negtq, *tmean, *ymean, *bnpart, *bnstat;
    cudaGetSymbolAddress((void**)&xT, s_xT);
    cudaGetSymbolAddress((void**)&pxT, s_pxT);
    cudaGetSymbolAddress((void**)&wth, s_wth);
    cudaGetSymbolAddress((void**)&wph, s_wph);
    cudaGetSymbolAddress((void**)&wg, s_wg);
    cudaGetSymbolAddress((void**)&wo, s_wo);
    cudaGetSymbolAddress((void**)&bth, s_bth);
    cudaGetSymbolAddress((void**)&thT, s_thT);
    cudaGetSymbolAddress((void**)&phT, s_phT);
    cudaGetSymbolAddress((void**)&gdev, s_gdev);
    cudaGetSymbolAddress((void**)&scoresh, s_scoresh);
    cudaGetSymbolAddress((void**)&p, s_p);
    cudaGetSymbolAddress((void**)&tdev, s_tdev);
    cudaGetSymbolAddress((void**)&pxsum, s_pxsum);
    cudaGetSymbolAddress((void**)&psum, s_psum);
    cudaGetSymbolAddress((void**)&gbias, s_gbias);
    cudaGetSymbolAddress((void**)&gmeanZ, s_gmeanZ);
    cudaGetSymbolAddress((void**)&negtq, s_negtq);
    cudaGetSymbolAddress((void**)&tmean, s_tmean);
    cudaGetSymbolAddress((void**)&ymean, s_ymean);
    cudaGetSymbolAddress((void**)&ydev, s_ydev);
    cudaGetSymbolAddress((void**)&bnpart, s_bnpart);
    cudaGetSymbolAddress((void**)&bnstat, s_bnstat);

    dim3 tb(32, 8);
    float scale = rsqrtf((float)CI_);

    // #1: converts + zeroing
    convert_all_kernel<<<(CI_ * C_ + 255) / 256, 256>>>(
        w_theta, w_phi, w_g, w_out, b_theta, wth, wph, wg, wo, bth, CI_ * C_, scale,
        pxsum, psum, bnpart);
    // #2, #3
    transpose_convert_kernel<<<dim3(N_ / 32, C_ / 32, B_), tb>>>(x, xT, C_, N_);
    pool_transpose_kernel<<<dim3(M_ / 32, C_ / 32, B_), tb>>>(x, pxT, pxsum);

    // #4 = GEMM1 (profiled by ncu): thT[n][ci] = xT @ (s*w_theta)^T + s*b_theta
    gemm_hf<1><<<dim3(CI_ / 256, N_ / 128, B_), 256, HF_SMEM>>>(
        xT, (long long)N_ * C_, C_,
        wth, 0, C_,
        nullptr, thT, (long long)N_ * CI_, CI_,
        C_, bth, 2, 0);
    // #5 gprep
    gprep_kernel<<<dim3(CI_, B_), 256>>>(w_g, pxsum, b_g, gbias, gmeanZ);
    // GEMM2: phT[m][ci]
    gemm_hf<1><<<dim3(CI_ / 256, M_ / 128, B_), 256, HF_SMEM>>>(
        pxT, (long long)M_ * C_, C_,
        wph, 0, C_,
        nullptr, phT, (long long)M_ * CI_, CI_,
        C_, b_phi, 2, 0);
    // GEMM3: centered gdev
    gemm_hf<1><<<dim3(M_ / 256, CI_ / 128, B_), 256, HF_SMEM>>>(
        wg, 0, C_,
        pxT, (long long)M_ * C_, C_,
        nullptr, gdev, (long long)CI_ * M_, M_,
        C_, gbias, 4, CI_);
    // GEMM4: pre-scaled scores
    gemm_hf<1><<<dim3(M_ / 256, N_ / 128, B_), 256, HF_SMEM>>>(
        thT, (long long)N_ * CI_, CI_,
        phT, (long long)M_ * CI_, CI_,
        nullptr, scoresh, (long long)N_ * M_, M_,
        CI_, nullptr, 0, 0);
    softmax_psum_kernel<<<dim3(N_ / 8, B_), 256>>>(scoresh, p, psum);
    tq_kernel<<<dim3(CI_, B_), 256>>>(gdev, psum, gmeanZ, negtq, tmean);
    // GEMM5: tdev
    gemm_hf<1><<<dim3(CI_ / 256, N_ / 128, B_), 256, HF_SMEM>>>(
        p, (long long)N_ * M_, M_,
        gdev, (long long)CI_ * M_, M_,
        nullptr, tdev, (long long)N_ * CI_, CI_,
        M_, negtq, 3, CI_);
    ymean_kernel<<<dim3(C_ / 256, B_), 256>>>(w_out, b_out, tmean, ymean);
    // GEMM6: ydev
    gemm_hf<1><<<dim3(C_ / 256, N_ / 128, B_), 256, HF_SMEM>>>(
        tdev, (long long)N_ * CI_, CI_,
        wo, 0, CI_,
        nullptr, ydev, (long long)N_ * C_, C_,
        CI_, nullptr, 0, 0);

    bn_stats_kernel<<<dim3(C_ / 128, B_, 8), 128>>>(ydev, bnpart);
    bn_final_kernel<<<4, 256>>>(bnpart, ymean, bnstat);
    bn_apply_kernel<<<dim3(N_ / 32, C_ / 32, B_), tb>>>(ydev, x, bnstat, ymean, gamma, beta, out);
}